// round 1
// baseline (speedup 1.0000x reference)
#include <cuda_runtime.h>
#include <stdint.h>

#define QPB   8          // queries per block (1 per warp)
#define CHUNK 2048       // refs staged in smem per iteration
#define CAP   128        // candidate buffer per query
#define KMAX  32
#define MMAX  32768

// Scratch: packed reference coords (x | y<<16, z). 256KB static device array.
__device__ uint2 g_packed[MMAX];

__global__ void pack_coords_kernel(const int* __restrict__ mid,
                                   const int* __restrict__ low,
                                   int M1, int M) {
    int i = blockIdx.x * blockDim.x + threadIdx.x;
    if (i >= M) return;
    const int* s = (i < M1) ? (mid + 3 * i) : (low + 3 * (i - M1));
    unsigned x = (unsigned)s[0];
    unsigned y = (unsigned)s[1];
    unsigned z = (unsigned)s[2];
    g_packed[i] = make_uint2(x | (y << 16), z);
}

// Warp-local prune: find exact k-th smallest d2 among cnt buffer entries via
// 24-step binary search on the integer value (d2 < 2^24), then compact all
// entries with d2 <= T to the front. Returns T (new append threshold).
// Invariant: any entry with d2 > T has >= k entries strictly smaller -> can
// never be in the true top-k, safe to discard.
__device__ __forceinline__ int warp_prune(uint2* buf, int* cntp, int k, int lane) {
    int cnt = *cntp;
    unsigned d2r[CAP / 32], idr[CAP / 32];
#pragma unroll
    for (int s = 0; s < CAP / 32; s++) {
        int i = s * 32 + lane;
        uint2 e = (i < cnt) ? buf[i] : make_uint2(0xffffffffu, 0u);
        d2r[s] = e.x; idr[s] = e.y;
    }
    unsigned lo = 0, hi = 0x00ffffffu;
    while (lo < hi) {
        unsigned mid = (lo + hi) >> 1;
        int c = 0;
#pragma unroll
        for (int s = 0; s < CAP / 32; s++) c += (d2r[s] <= mid) ? 1 : 0;
        c = __reduce_add_sync(0xffffffffu, c);
        if (c >= k) hi = mid; else lo = mid + 1;
    }
    unsigned T = lo;
    int base = 0;
#pragma unroll
    for (int s = 0; s < CAP / 32; s++) {
        bool keep = (d2r[s] <= T);   // padded entries (0xffffffff) never kept
        unsigned m = __ballot_sync(0xffffffffu, keep);
        int pos = base + __popc(m & ((1u << lane) - 1u));
        if (keep && pos < CAP) buf[pos] = make_uint2(d2r[s], idr[s]);
        base += __popc(m);
    }
    if (lane == 0) *cntp = (base < CAP) ? base : CAP;
    __syncwarp();
    return (int)T;
}

__global__ __launch_bounds__(256)
void knn_fuse_kernel(const int* __restrict__ qc,
                     const float* __restrict__ midf,
                     const float* __restrict__ lowf,
                     const int* __restrict__ kp,
                     float* __restrict__ out,
                     int N, int M1, int M, int D) {
    __shared__ uint2    s_chunk[CHUNK];
    __shared__ uint2    s_buf[QPB][CAP];
    __shared__ int      s_cnt[QPB];
    __shared__ int      s_selidx[QPB][KMAX];
    __shared__ unsigned s_seld2[QPB][KMAX];
    __shared__ float    s_wt[QPB][KMAX];

    const int tid  = threadIdx.x;
    const int w    = tid >> 5;
    const int lane = tid & 31;
    const int k    = kp ? min(*kp, KMAX) : 24;

    const int q = blockIdx.x * QPB + w;
    const bool active = (q < N);

    int qx = 0, qy = 0, qz = 0;
    if (active) { qx = qc[3 * q]; qy = qc[3 * q + 1]; qz = qc[3 * q + 2]; }
    if (lane == 0) s_cnt[w] = 0;
    __syncthreads();

    int T = 0x7fffffff;

    for (int c0 = 0; c0 < M; c0 += CHUNK) {
        const int cn = min(CHUNK, M - c0);
        for (int i = tid; i < cn; i += 256) s_chunk[i] = g_packed[c0 + i];
        __syncthreads();

        if (active) {
            for (int i0 = 0; i0 < cn; i0 += 64) {   // sub-batch: <=64 appends between checks
#pragma unroll
                for (int u = 0; u < 2; u++) {
                    int i = i0 + u * 32 + lane;
                    if (i < cn) {
                        uint2 p = s_chunk[i];
                        int dx = qx - (int)(p.x & 0xffffu);
                        int dy = qy - (int)(p.x >> 16);
                        int dz = qz - (int)p.y;
                        int d2 = dx * dx + dy * dy + dz * dz;
                        if (d2 <= T) {
                            int pos = atomicAdd(&s_cnt[w], 1);
                            if (pos < CAP)
                                s_buf[w][pos] = make_uint2((unsigned)d2, (unsigned)(c0 + i));
                        }
                    }
                }
                __syncwarp();
                if (s_cnt[w] > CAP - 64)
                    T = warp_prune(&s_buf[w][0], &s_cnt[w], k, lane);
            }
        }
        __syncthreads();
    }

    // ----- final exact top-k by composite key (d2, idx): stable-tie like lax.top_k -----
    if (active) {
        const int cnt = s_cnt[w];
        unsigned d2r[CAP / 32], idr[CAP / 32];
        unsigned long long keyr[CAP / 32];
#pragma unroll
        for (int s = 0; s < CAP / 32; s++) {
            int i = s * 32 + lane;
            uint2 e = (i < cnt) ? s_buf[w][i] : make_uint2(0xffffffffu, 0xffffffffu);
            d2r[s] = e.x; idr[s] = e.y;
            keyr[s] = ((unsigned long long)e.x << 32) | (unsigned long long)e.y;
        }
        int rk[CAP / 32];
#pragma unroll
        for (int s = 0; s < CAP / 32; s++) rk[s] = 0;
        for (int j = 0; j < cnt; j++) {
            uint2 ej = s_buf[w][j];                 // same addr across lanes: LDS broadcast
            unsigned long long kj = ((unsigned long long)ej.x << 32) | (unsigned long long)ej.y;
#pragma unroll
            for (int s = 0; s < CAP / 32; s++) rk[s] += (kj < keyr[s]) ? 1 : 0;
        }
#pragma unroll
        for (int s = 0; s < CAP / 32; s++) {
            int i = s * 32 + lane;
            if (i < cnt && rk[s] < k) {             // ranks are unique & dense in [0,k)
                s_selidx[w][rk[s]] = (int)idr[s];
                s_seld2[w][rk[s]]  = d2r[s];
            }
        }
        __syncwarp();

        float wj = 0.0f;
        if (lane < k) wj = 1.0f / (1.0f + sqrtf((float)s_seld2[w][lane]));
        float tot = wj;
#pragma unroll
        for (int o = 16; o > 0; o >>= 1) tot += __shfl_xor_sync(0xffffffffu, tot, o);
        if (lane < k) s_wt[w][lane] = wj / tot;
        __syncwarp();
    }
    __syncthreads();

    // ----- weighted feature gather -----
    if (active) {
        if (D == 128) {
            float4 acc = make_float4(0.f, 0.f, 0.f, 0.f);
            for (int j = 0; j < k; j++) {
                int   si = s_selidx[w][j];
                float wt = s_wt[w][j];
                const float* f = (si < M1) ? (midf + (size_t)si * 128)
                                           : (lowf + (size_t)(si - M1) * 128);
                float4 v = *(const float4*)(f + lane * 4);
                acc.x += wt * v.x; acc.y += wt * v.y;
                acc.z += wt * v.z; acc.w += wt * v.w;
            }
            *(float4*)(out + (size_t)q * 128 + lane * 4) = acc;
        } else {
            for (int d = lane; d < D; d += 32) {
                float a = 0.f;
                for (int j = 0; j < k; j++) {
                    int   si = s_selidx[w][j];
                    float wt = s_wt[w][j];
                    const float* f = (si < M1) ? (midf + (size_t)si * D)
                                               : (lowf + (size_t)(si - M1) * D);
                    a += wt * f[d];
                }
                out[(size_t)q * D + d] = a;
            }
        }
    }
}

extern "C" void kernel_launch(void* const* d_in, const int* in_sizes, int n_in,
                              void* d_out, int out_size) {
    const int*   qc   = (const int*)d_in[0];
    const int*   midc = (const int*)d_in[1];
    const int*   lowc = (const int*)d_in[2];
    const float* midf = (const float*)d_in[3];
    const float* lowf = (const float*)d_in[4];
    const int*   kp   = (n_in >= 6) ? (const int*)d_in[5] : nullptr;

    const int N  = in_sizes[0] / 3;
    const int M1 = in_sizes[1] / 3;
    const int M2 = in_sizes[2] / 3;
    const int M  = M1 + M2;
    const int D  = (M1 > 0) ? in_sizes[3] / M1 : 128;

    pack_coords_kernel<<<(M + 255) / 256, 256>>>(midc, lowc, M1, M);
    knn_fuse_kernel<<<(N + QPB - 1) / QPB, 256>>>(qc, midf, lowf, kp,
                                                  (float*)d_out, N, M1, M, D);
}

// round 2
// speedup vs baseline: 4.7278x; 4.7278x over previous
#include <cuda_runtime.h>
#include <stdint.h>

#define QPB   8          // queries per block (1 per warp)
#define CAP   256        // candidate buffer per query
#define KMAX  32
#define MMAX  32768
#define GC    27         // grid cells per axis (1728/64)
#define NC    (GC*GC*GC) // 19683
#define CSH   6          // log2(cell size 64)

// ---- device scratch (no allocs allowed) ----
__device__ int   g_cellcnt[NC];
__device__ int   g_cellstart[NC + 1];
__device__ uint2 g_pts[MMAX];   // sorted by cell: .x = x|y<<16, .y = z|idx<<16

__device__ __forceinline__ int cell_of(int x, int y, int z) {
    return (x >> CSH) + GC * (y >> CSH) + GC * GC * (z >> CSH);
}

__global__ void reset_kernel() {
    int i = blockIdx.x * blockDim.x + threadIdx.x;
    if (i < NC) g_cellcnt[i] = 0;
}

__global__ void hist_kernel(const int* __restrict__ mid, const int* __restrict__ low,
                            int M1, int M) {
    int i = blockIdx.x * blockDim.x + threadIdx.x;
    if (i >= M) return;
    const int* s = (i < M1) ? (mid + 3 * i) : (low + 3 * (i - M1));
    atomicAdd(&g_cellcnt[cell_of(s[0], s[1], s[2])], 1);
}

// single block: exclusive prefix over 19683 cell counts, then re-zero counts
__global__ void scan_kernel(int M) {
    __shared__ int s_sum[1024];
    const int t = threadIdx.x;
    const int PER = (NC + 1023) / 1024;   // 20
    const int base = t * PER;
    int sum = 0;
    for (int j = 0; j < PER; j++) { int c = base + j; if (c < NC) sum += g_cellcnt[c]; }
    s_sum[t] = sum;
    __syncthreads();
    for (int off = 1; off < 1024; off <<= 1) {
        int v = (t >= off) ? s_sum[t - off] : 0;
        __syncthreads();
        s_sum[t] += v;
        __syncthreads();
    }
    int run = (t == 0) ? 0 : s_sum[t - 1];
    for (int j = 0; j < PER; j++) {
        int c = base + j;
        if (c < NC) { g_cellstart[c] = run; run += g_cellcnt[c]; }
    }
    if (t == 1023) g_cellstart[NC] = s_sum[1023];
    __syncthreads();
    for (int c = t; c < NC; c += 1024) g_cellcnt[c] = 0;  // reuse as scatter offsets
}

__global__ void scatter_kernel(const int* __restrict__ mid, const int* __restrict__ low,
                               int M1, int M) {
    int i = blockIdx.x * blockDim.x + threadIdx.x;
    if (i >= M) return;
    const int* s = (i < M1) ? (mid + 3 * i) : (low + 3 * (i - M1));
    int x = s[0], y = s[1], z = s[2];
    int c = cell_of(x, y, z);
    int pos = g_cellstart[c] + atomicAdd(&g_cellcnt[c], 1);
    g_pts[pos] = make_uint2((unsigned)x | ((unsigned)y << 16),
                            (unsigned)z | ((unsigned)i << 16));
}

// Exact k-th select (binary search on integer d2 < 2^24), then compact entries
// with d2 <= T to front. Returns T; updates cnt (warp-uniform). Keeps all ties.
__device__ __forceinline__ int warp_prune(uint2* buf, int& cnt, int k, int lane) {
    unsigned d2r[CAP / 32], idr[CAP / 32];
#pragma unroll
    for (int s = 0; s < CAP / 32; s++) {
        int i = s * 32 + lane;
        uint2 e = (i < cnt) ? buf[i] : make_uint2(0x7fffffffu, 0u);
        d2r[s] = e.x; idr[s] = e.y;
    }
    unsigned lo = 0, hi = 0x00ffffffu;
    while (lo < hi) {
        unsigned mid = (lo + hi) >> 1;
        int c = 0;
#pragma unroll
        for (int s = 0; s < CAP / 32; s++) c += (d2r[s] <= mid) ? 1 : 0;
        c = __reduce_add_sync(0xffffffffu, c);
        if (c >= k) hi = mid; else lo = mid + 1;
    }
    unsigned T = lo;
    int base = 0;
#pragma unroll
    for (int s = 0; s < CAP / 32; s++) {
        bool keep = (d2r[s] <= T);
        unsigned m = __ballot_sync(0xffffffffu, keep);
        if (keep) buf[base + __popc(m & ((1u << lane) - 1u))] = make_uint2(d2r[s], idr[s]);
        base += __popc(m);
    }
    __syncwarp();
    cnt = base;
    return (int)T;
}

__global__ __launch_bounds__(256)
void knn_query_kernel(const int* __restrict__ qc,
                      const float* __restrict__ midf,
                      const float* __restrict__ lowf,
                      const int* __restrict__ kp,
                      float* __restrict__ out,
                      int N, int M1, int D) {
    __shared__ uint2    s_buf[QPB][CAP];
    __shared__ int      s_base[QPB][32];
    __shared__ int      s_pref[QPB][33];
    __shared__ int      s_selidx[QPB][KMAX];
    __shared__ unsigned s_seld2[QPB][KMAX];
    __shared__ float    s_wt[QPB][KMAX];

    const unsigned FULL = 0xffffffffu;
    const int tid = threadIdx.x;
    const int w = tid >> 5;
    const int lane = tid & 31;
    const unsigned lmlt = (1u << lane) - 1u;
    const int kk = kp ? min(*kp, KMAX) : 24;

    const int q = blockIdx.x * QPB + w;
    if (q >= N) return;                         // whole warp exits together

    const int qx = qc[3 * q], qy = qc[3 * q + 1], qz = qc[3 * q + 2];
    const int qcx = min(qx >> CSH, GC - 1);
    const int qcy = min(qy >> CSH, GC - 1);
    const int qcz = min(qz >> CSH, GC - 1);

    int cnt = 0;
    int T = 0x7fffffff;

    for (int s = 0; s < GC; s++) {
        const int side = 2 * s + 1;
        const int ncube = side * side * side;
        for (int b = 0; b < ncube; b += 32) {
            int t = b + lane;
            int ccnt = 0, cbase = 0;
            if (t < ncube) {
                int di = t % side - s;
                int r1 = t / side;
                int dj = r1 % side - s;
                int dk = r1 / side - s;
                int cheb = max(abs(di), max(abs(dj), abs(dk)));
                int ci = qcx + di, cj = qcy + dj, ck = qcz + dk;
                if (cheb == s && ci >= 0 && ci < GC && cj >= 0 && cj < GC
                               && ck >= 0 && ck < GC) {
                    int lx = ci << CSH, ly = cj << CSH, lz = ck << CSH;
                    int mdx = max(0, max(lx - qx, qx - (lx + 63)));
                    int mdy = max(0, max(ly - qy, qy - (ly + 63)));
                    int mdz = max(0, max(lz - qz, qz - (lz + 63)));
                    int md2 = mdx * mdx + mdy * mdy + mdz * mdz;
                    if (md2 <= T) {
                        int cell = ci + GC * cj + GC * GC * ck;
                        int st = g_cellstart[cell];
                        ccnt = g_cellstart[cell + 1] - st;
                        cbase = st;
                    }
                }
            }
            // warp inclusive scan of ccnt
            int inc = ccnt;
#pragma unroll
            for (int off = 1; off < 32; off <<= 1) {
                int v = __shfl_up_sync(FULL, inc, off);
                if (lane >= off) inc += v;
            }
            int P = __shfl_sync(FULL, inc, 31);
            if (P == 0) continue;
            if (lane == 0) s_pref[w][0] = 0;
            s_pref[w][lane + 1] = inc;
            s_base[w][lane] = cbase - (inc - ccnt);   // pbase: point = g_pts[pbase + t2]
            __syncwarp();

            const int nb = (P + 31) >> 5;
            for (int it = 0; it < nb; it++) {
                int t2 = it * 32 + lane;
                bool valid = (t2 < P);
                int d2 = 0; unsigned pidx = 0;
                if (valid) {
                    int j = 0;
#pragma unroll
                    for (int step = 16; step >= 1; step >>= 1) {
                        int cand = j + step;
                        if (s_pref[w][cand] <= t2) j = cand;
                    }
                    uint2 p = g_pts[s_base[w][j] + t2];
                    int px = (int)(p.x & 0xffffu);
                    int py = (int)(p.x >> 16);
                    int pz = (int)(p.y & 0xffffu);
                    int dx = qx - px, dy = qy - py, dz = qz - pz;
                    d2 = dx * dx + dy * dy + dz * dz;
                    pidx = p.y >> 16;
                }
                bool hit = valid && (d2 <= T);
                unsigned m = __ballot_sync(FULL, hit);
                if (hit) s_buf[w][cnt + __popc(m & lmlt)] = make_uint2((unsigned)d2, pidx);
                cnt += __popc(m);
                if (cnt > CAP - 32) T = warp_prune(&s_buf[w][0], cnt, kk, lane);
            }
            __syncwarp();
        }
        // ring finished: tighten T, then test provable lower bound of ring s+1
        if (cnt >= kk) {
            T = warp_prune(&s_buf[w][0], cnt, kk, lane);
            int bnd = s << CSH;                 // ring s+1 min dist > s*64
            if (bnd * bnd >= T) break;
        }
    }

    // ----- final exact top-k by composite key (d2, idx): stable ties -----
    const int kk2 = min(kk, cnt);
    {
        unsigned d2r[CAP / 32], idr[CAP / 32];
        unsigned long long keyr[CAP / 32];
        int rk[CAP / 32];
#pragma unroll
        for (int s = 0; s < CAP / 32; s++) {
            int i = s * 32 + lane;
            uint2 e = (i < cnt) ? s_buf[w][i] : make_uint2(0xffffffffu, 0xffffffffu);
            d2r[s] = e.x; idr[s] = e.y;
            keyr[s] = ((unsigned long long)e.x << 32) | (unsigned long long)e.y;
            rk[s] = 0;
        }
        for (int jj = 0; jj < cnt; jj++) {
            uint2 ej = s_buf[w][jj];            // uniform addr: LDS broadcast
            unsigned long long kj = ((unsigned long long)ej.x << 32)
                                  | (unsigned long long)ej.y;
#pragma unroll
            for (int s = 0; s < CAP / 32; s++) rk[s] += (kj < keyr[s]) ? 1 : 0;
        }
#pragma unroll
        for (int s = 0; s < CAP / 32; s++) {
            int i = s * 32 + lane;
            if (i < cnt && rk[s] < kk2) {
                s_selidx[w][rk[s]] = (int)idr[s];
                s_seld2[w][rk[s]]  = d2r[s];
            }
        }
        __syncwarp();
    }

    float wj = 0.0f;
    if (lane < kk2) wj = 1.0f / (1.0f + sqrtf((float)s_seld2[w][lane]));
    float tot = wj;
#pragma unroll
    for (int o = 16; o > 0; o >>= 1) tot += __shfl_xor_sync(FULL, tot, o);
    if (lane < kk2) s_wt[w][lane] = wj / tot;
    __syncwarp();

    // ----- weighted feature gather -----
    if (D == 128) {
        float4 acc = make_float4(0.f, 0.f, 0.f, 0.f);
        for (int j = 0; j < kk2; j++) {
            int   si = s_selidx[w][j];
            float wt = s_wt[w][j];
            const float* f = (si < M1) ? (midf + (size_t)si * 128)
                                       : (lowf + (size_t)(si - M1) * 128);
            float4 v = *(const float4*)(f + lane * 4);
            acc.x += wt * v.x; acc.y += wt * v.y;
            acc.z += wt * v.z; acc.w += wt * v.w;
        }
        *(float4*)(out + (size_t)q * 128 + lane * 4) = acc;
    } else {
        for (int d = lane; d < D; d += 32) {
            float a = 0.f;
            for (int j = 0; j < kk2; j++) {
                int   si = s_selidx[w][j];
                float wt = s_wt[w][j];
                const float* f = (si < M1) ? (midf + (size_t)si * D)
                                           : (lowf + (size_t)(si - M1) * D);
                a += wt * f[d];
            }
            out[(size_t)q * D + d] = a;
        }
    }
}

extern "C" void kernel_launch(void* const* d_in, const int* in_sizes, int n_in,
                              void* d_out, int out_size) {
    const int*   qc   = (const int*)d_in[0];
    const int*   midc = (const int*)d_in[1];
    const int*   lowc = (const int*)d_in[2];
    const float* midf = (const float*)d_in[3];
    const float* lowf = (const float*)d_in[4];
    const int*   kp   = (n_in >= 6) ? (const int*)d_in[5] : nullptr;

    const int N  = in_sizes[0] / 3;
    const int M1 = in_sizes[1] / 3;
    const int M2 = in_sizes[2] / 3;
    const int M  = M1 + M2;
    const int D  = (M1 > 0) ? in_sizes[3] / M1 : 128;

    reset_kernel<<<(NC + 255) / 256, 256>>>();
    hist_kernel<<<(M + 255) / 256, 256>>>(midc, lowc, M1, M);
    scan_kernel<<<1, 1024>>>(M);
    scatter_kernel<<<(M + 255) / 256, 256>>>(midc, lowc, M1, M);
    knn_query_kernel<<<(N + QPB - 1) / QPB, 256>>>(qc, midf, lowf, kp,
                                                   (float*)d_out, N, M1, D);
}

// round 3
// speedup vs baseline: 6.9455x; 1.4691x over previous
#include <cuda_runtime.h>
#include <stdint.h>

#define QPB   8          // queries per block (1 per warp)
#define CAP   128        // candidate buffer per query
#define KMAX  32
#define MMAX  32768
#define GC    27         // grid cells per axis (1728/64)
#define NC    (GC*GC*GC) // 19683
#define CSH   6          // log2(cell size 64)
#define BCAP  64         // bucket capacity per cell

// ---- device scratch (no allocs allowed) ----
__device__ int   g_cellcnt[NC];
__device__ uint2 g_pts[NC * BCAP];   // bucketed: .x = x|y<<16, .y = z|idx<<16
__device__ int   g_ovcnt;
__device__ uint2 g_ov[MMAX];         // overflow (exactness fallback; empty in practice)

__device__ __forceinline__ int cell_of(int x, int y, int z) {
    return (x >> CSH) + GC * (y >> CSH) + GC * GC * (z >> CSH);
}

__global__ void reset_kernel() {
    int i = blockIdx.x * blockDim.x + threadIdx.x;
    if (i < NC) g_cellcnt[i] = 0;
    if (i == 0) g_ovcnt = 0;
}

__global__ void build_kernel(const int* __restrict__ mid, const int* __restrict__ low,
                             int M1, int M) {
    int i = blockIdx.x * blockDim.x + threadIdx.x;
    if (i >= M) return;
    const int* s = (i < M1) ? (mid + 3 * i) : (low + 3 * (i - M1));
    int x = s[0], y = s[1], z = s[2];
    int c = cell_of(x, y, z);
    uint2 pt = make_uint2((unsigned)x | ((unsigned)y << 16),
                          (unsigned)z | ((unsigned)i << 16));
    int pos = atomicAdd(&g_cellcnt[c], 1);
    if (pos < BCAP) g_pts[c * BCAP + pos] = pt;
    else            g_ov[atomicAdd(&g_ovcnt, 1)] = pt;
}

// Exact k-th select (binary search on integer d2 < 2^24), then compact entries
// with d2 <= T to front. Returns T; updates cnt (warp-uniform). Keeps all ties.
__device__ __forceinline__ int warp_prune(uint2* buf, int& cnt, int k, int lane) {
    unsigned d2r[CAP / 32], idr[CAP / 32];
#pragma unroll
    for (int s = 0; s < CAP / 32; s++) {
        int i = s * 32 + lane;
        uint2 e = (i < cnt) ? buf[i] : make_uint2(0x7fffffffu, 0u);
        d2r[s] = e.x; idr[s] = e.y;
    }
    unsigned lo = 0, hi = 0x00ffffffu;
    while (lo < hi) {
        unsigned mid = (lo + hi) >> 1;
        int c = 0;
#pragma unroll
        for (int s = 0; s < CAP / 32; s++) c += (d2r[s] <= mid) ? 1 : 0;
        c = __reduce_add_sync(0xffffffffu, c);
        if (c >= k) hi = mid; else lo = mid + 1;
    }
    unsigned T = lo;
    int base = 0;
#pragma unroll
    for (int s = 0; s < CAP / 32; s++) {
        bool keep = (d2r[s] <= T);
        unsigned m = __ballot_sync(0xffffffffu, keep);
        if (keep) buf[base + __popc(m & ((1u << lane) - 1u))] = make_uint2(d2r[s], idr[s]);
        base += __popc(m);
    }
    __syncwarp();
    cnt = base;
    return (int)T;
}

__global__ __launch_bounds__(256)
void knn_query_kernel(const int* __restrict__ qc,
                      const float* __restrict__ midf,
                      const float* __restrict__ lowf,
                      const int* __restrict__ kp,
                      float* __restrict__ out,
                      int N, int M1, int D) {
    __shared__ uint2    s_buf[QPB][CAP];
    __shared__ int      s_base[QPB][32];
    __shared__ int      s_pref[QPB][33];
    __shared__ int      s_selidx[QPB][KMAX];
    __shared__ unsigned s_seld2[QPB][KMAX];
    __shared__ float    s_wt[QPB][KMAX];

    const unsigned FULL = 0xffffffffu;
    const int tid = threadIdx.x;
    const int w = tid >> 5;
    const int lane = tid & 31;
    const unsigned lmlt = (1u << lane) - 1u;
    const int kk = kp ? min(*kp, KMAX) : 24;

    const int q = blockIdx.x * QPB + w;
    if (q >= N) return;                         // whole warp exits together

    const int qx = qc[3 * q], qy = qc[3 * q + 1], qz = qc[3 * q + 2];
    const int qcx = min(qx >> CSH, GC - 1);
    const int qcy = min(qy >> CSH, GC - 1);
    const int qcz = min(qz >> CSH, GC - 1);

    int cnt = 0;
    int T = 0x7fffffff;

    // ---- overflow fallback (empty unless some bucket spilled) ----
    const int ov = g_ovcnt;
    for (int b = 0; b < ov; b += 32) {
        int i = b + lane;
        bool valid = (i < ov);
        int d2 = 0; unsigned pidx = 0;
        if (valid) {
            uint2 p = g_ov[i];
            int dx = qx - (int)(p.x & 0xffffu);
            int dy = qy - (int)(p.x >> 16);
            int dz = qz - (int)(p.y & 0xffffu);
            d2 = dx * dx + dy * dy + dz * dz;
            pidx = p.y >> 16;
        }
        bool hit = valid && (d2 <= T);
        unsigned m = __ballot_sync(FULL, hit);
        if (hit) s_buf[w][cnt + __popc(m & lmlt)] = make_uint2((unsigned)d2, pidx);
        cnt += __popc(m);
        if (cnt > CAP - 32) T = warp_prune(&s_buf[w][0], cnt, kk, lane);
    }

    // ---- expanding ring scan ----
    for (int s = 0; s < GC; s++) {
        const int side = 2 * s + 1;
        const int ncube = side * side * side;
        for (int b = 0; b < ncube; b += 32) {
            int t = b + lane;
            int ccnt = 0, cbase = 0;
            if (t < ncube) {
                int di = t % side - s;
                int r1 = t / side;
                int dj = r1 % side - s;
                int dk = r1 / side - s;
                int cheb = max(abs(di), max(abs(dj), abs(dk)));
                int ci = qcx + di, cj = qcy + dj, ck = qcz + dk;
                if (cheb == s && ci >= 0 && ci < GC && cj >= 0 && cj < GC
                               && ck >= 0 && ck < GC) {
                    int lx = ci << CSH, ly = cj << CSH, lz = ck << CSH;
                    int mdx = max(0, max(lx - qx, qx - (lx + 63)));
                    int mdy = max(0, max(ly - qy, qy - (ly + 63)));
                    int mdz = max(0, max(lz - qz, qz - (lz + 63)));
                    int md2 = mdx * mdx + mdy * mdy + mdz * mdz;
                    if (md2 <= T) {
                        int cell = ci + GC * cj + GC * GC * ck;
                        ccnt = min(g_cellcnt[cell], BCAP);
                        cbase = cell * BCAP;
                    }
                }
            }
            // warp inclusive scan of ccnt
            int inc = ccnt;
#pragma unroll
            for (int off = 1; off < 32; off <<= 1) {
                int v = __shfl_up_sync(FULL, inc, off);
                if (lane >= off) inc += v;
            }
            int P = __shfl_sync(FULL, inc, 31);
            if (P == 0) continue;
            if (lane == 0) s_pref[w][0] = 0;
            s_pref[w][lane + 1] = inc;
            s_base[w][lane] = cbase - (inc - ccnt);   // point = g_pts[base + t2]
            __syncwarp();

            const int nb = (P + 31) >> 5;
            for (int it = 0; it < nb; it++) {
                int t2 = it * 32 + lane;
                bool valid = (t2 < P);
                int d2 = 0; unsigned pidx = 0;
                if (valid) {
                    int j = 0;
#pragma unroll
                    for (int step = 16; step >= 1; step >>= 1) {
                        int cand = j + step;
                        if (s_pref[w][cand] <= t2) j = cand;
                    }
                    uint2 p = g_pts[s_base[w][j] + t2];
                    int dx = qx - (int)(p.x & 0xffffu);
                    int dy = qy - (int)(p.x >> 16);
                    int dz = qz - (int)(p.y & 0xffffu);
                    d2 = dx * dx + dy * dy + dz * dz;
                    pidx = p.y >> 16;
                }
                bool hit = valid && (d2 <= T);
                unsigned m = __ballot_sync(FULL, hit);
                if (hit) s_buf[w][cnt + __popc(m & lmlt)] = make_uint2((unsigned)d2, pidx);
                cnt += __popc(m);
                if (cnt > CAP - 32) T = warp_prune(&s_buf[w][0], cnt, kk, lane);
            }
            __syncwarp();
        }
        // ring finished: tighten T, then test provable lower bound of ring s+1
        if (cnt >= kk) {
            T = warp_prune(&s_buf[w][0], cnt, kk, lane);
            int bnd = s << CSH;                 // ring s+1 min dist > s*64
            if (bnd * bnd >= T) break;
        }
    }

    // ----- final exact top-k by composite key (d2, idx): stable ties -----
    const int kk2 = min(kk, cnt);
    {
        unsigned d2r[CAP / 32], idr[CAP / 32];
        unsigned long long keyr[CAP / 32];
        int rk[CAP / 32];
#pragma unroll
        for (int s = 0; s < CAP / 32; s++) {
            int i = s * 32 + lane;
            uint2 e = (i < cnt) ? s_buf[w][i] : make_uint2(0xffffffffu, 0xffffffffu);
            d2r[s] = e.x; idr[s] = e.y;
            keyr[s] = ((unsigned long long)e.x << 32) | (unsigned long long)e.y;
            rk[s] = 0;
        }
        for (int jj = 0; jj < cnt; jj++) {
            uint2 ej = s_buf[w][jj];            // uniform addr: LDS broadcast
            unsigned long long kj = ((unsigned long long)ej.x << 32)
                                  | (unsigned long long)ej.y;
#pragma unroll
            for (int s = 0; s < CAP / 32; s++) rk[s] += (kj < keyr[s]) ? 1 : 0;
        }
#pragma unroll
        for (int s = 0; s < CAP / 32; s++) {
            int i = s * 32 + lane;
            if (i < cnt && rk[s] < kk2) {
                s_selidx[w][rk[s]] = (int)idr[s];
                s_seld2[w][rk[s]]  = d2r[s];
            }
        }
        __syncwarp();
    }

    float wj = 0.0f;
    if (lane < kk2) wj = 1.0f / (1.0f + sqrtf((float)s_seld2[w][lane]));
    float tot = wj;
#pragma unroll
    for (int o = 16; o > 0; o >>= 1) tot += __shfl_xor_sync(FULL, tot, o);
    if (lane < kk2) s_wt[w][lane] = wj / tot;
    __syncwarp();

    // ----- weighted feature gather -----
    if (D == 128) {
        float4 acc = make_float4(0.f, 0.f, 0.f, 0.f);
        for (int j = 0; j < kk2; j++) {
            int   si = s_selidx[w][j];
            float wt = s_wt[w][j];
            const float* f = (si < M1) ? (midf + (size_t)si * 128)
                                       : (lowf + (size_t)(si - M1) * 128);
            float4 v = *(const float4*)(f + lane * 4);
            acc.x += wt * v.x; acc.y += wt * v.y;
            acc.z += wt * v.z; acc.w += wt * v.w;
        }
        *(float4*)(out + (size_t)q * 128 + lane * 4) = acc;
    } else {
        for (int d = lane; d < D; d += 32) {
            float a = 0.f;
            for (int j = 0; j < kk2; j++) {
                int   si = s_selidx[w][j];
                float wt = s_wt[w][j];
                const float* f = (si < M1) ? (midf + (size_t)si * D)
                                           : (lowf + (size_t)(si - M1) * D);
                a += wt * f[d];
            }
            out[(size_t)q * D + d] = a;
        }
    }
}

extern "C" void kernel_launch(void* const* d_in, const int* in_sizes, int n_in,
                              void* d_out, int out_size) {
    const int*   qc   = (const int*)d_in[0];
    const int*   midc = (const int*)d_in[1];
    const int*   lowc = (const int*)d_in[2];
    const float* midf = (const float*)d_in[3];
    const float* lowf = (const float*)d_in[4];
    const int*   kp   = (n_in >= 6) ? (const int*)d_in[5] : nullptr;

    const int N  = in_sizes[0] / 3;
    const int M1 = in_sizes[1] / 3;
    const int M2 = in_sizes[2] / 3;
    const int M  = M1 + M2;
    const int D  = (M1 > 0) ? in_sizes[3] / M1 : 128;

    reset_kernel<<<(NC + 255) / 256, 256>>>();
    build_kernel<<<(M + 255) / 256, 256>>>(midc, lowc, M1, M);
    knn_query_kernel<<<(N + QPB - 1) / QPB, 256>>>(qc, midf, lowf, kp,
                                                   (float*)d_out, N, M1, D);
}